// round 13
// baseline (speedup 1.0000x reference)
#include <cuda_runtime.h>
#include <math.h>
#include <stdint.h>

#define N_NODES 50000
#define E_MAX   800000
#define F_IN    256
#define F_OUT   128
#define ALPHA   0.2f
#define BUCKET  64          // slots per node; mean deg 16, sigma 4 -> 12-sigma margin

#define GTILE_M 64
#define KCHUNK  64
#define NCHUNKS (F_IN / KCHUNK)                       // 4
#define NTILES  ((N_NODES + GTILE_M - 1) / GTILE_M)   // 782
#define WSSTRIDE (NCHUNKS * F_OUT * KCHUNK)           // 32768

// smem: 3 A-split tiles (64x128B = 8KB) + 3 B-split tiles (128x128B = 16KB)
#define ATILEB  8192
#define BTILEB  16384
#define A_OFF(s) ((s) * ATILEB)
#define B_OFF(s) (3 * ATILEB + (s) * BTILEB)
#define SMEM_TOTAL (3 * ATILEB + 3 * BTILEB)          // 73728

// setup kernel grid split
#define ZBLK ((N_NODES + 255) / 256)                  // 196
#define WBLK ((F_IN * F_OUT + 255) / 256)             // 128

// Scratch (__device__ globals: allocation-free)
__device__ float g_h[N_NODES * F_OUT];
__device__ float g_lin_s[N_NODES];
__device__ float g_lin_d[N_NODES];
__device__ float g_asum[2 * F_OUT];
__device__ unsigned short g_wb[3 * WSSTRIDE];   // [split][chunk][n][kk]
__device__ int g_deg[N_NODES];
__device__ int g_edst[N_NODES * BUCKET];        // bucketed adjacency

// ---------------------------------------------------------------------------
__device__ __forceinline__ uint32_t smem_u32(const void* p) {
    uint32_t a;
    asm("{ .reg .u64 t; cvta.to.shared.u64 t, %1; cvt.u32.u64 %0, t; }"
        : "=r"(a) : "l"(p));
    return a;
}

__device__ __forceinline__ void ldsm4(uint32_t* r, uint32_t addr) {
    asm volatile("ldmatrix.sync.aligned.m8n8.x4.shared.b16 {%0,%1,%2,%3}, [%4];"
                 : "=r"(r[0]), "=r"(r[1]), "=r"(r[2]), "=r"(r[3]) : "r"(addr));
}

__device__ __forceinline__ void mma16816(float* d, const uint32_t* a, const uint32_t* b) {
    asm volatile(
        "mma.sync.aligned.m16n8k16.row.col.f32.bf16.bf16.f32 "
        "{%0,%1,%2,%3},{%4,%5,%6,%7},{%8,%9},{%0,%1,%2,%3};"
        : "+f"(d[0]), "+f"(d[1]), "+f"(d[2]), "+f"(d[3])
        : "r"(a[0]), "r"(a[1]), "r"(a[2]), "r"(a[3]), "r"(b[0]), "r"(b[1]));
}

// exact 3-way bf16 truncation split: v == b0 + b1 + b2 (+ ~2^-24 residual)
__device__ __forceinline__ void split3(float v, uint32_t& b0, uint32_t& b1, uint32_t& b2) {
    uint32_t u = __float_as_uint(v);
    b0 = u >> 16;
    float r1 = v - __uint_as_float(u & 0xFFFF0000u);
    uint32_t u1 = __float_as_uint(r1);
    b1 = u1 >> 16;
    float r2 = r1 - __uint_as_float(u1 & 0xFFFF0000u);
    b2 = __float_as_uint(r2) >> 16;
}

// ---------------------------------------------------------------------------
// Setup: zero degrees | split W | asum  (independent work, one launch)
// ---------------------------------------------------------------------------
__global__ void setup_kernel(const float* __restrict__ W,
                             const float* __restrict__ a) {
    int bid = blockIdx.x;
    if (bid < ZBLK) {
        int i = bid * 256 + threadIdx.x;
        if (i < N_NODES) g_deg[i] = 0;
    } else if (bid < ZBLK + WBLK) {
        int i = (bid - ZBLK) * 256 + threadIdx.x;
        if (i < F_IN * F_OUT) {
            int k = i >> 7, n = i & 127;
            uint32_t b0, b1, b2;
            split3(W[i], b0, b1, b2);
            int base = ((k >> 6) * F_OUT + n) * KCHUNK + (k & 63);
            g_wb[base]                = (unsigned short)b0;
            g_wb[WSSTRIDE + base]     = (unsigned short)b1;
            g_wb[2 * WSSTRIDE + base] = (unsigned short)b2;
        }
    } else {
        int c = threadIdx.x;
        float s = 0.f;
        #pragma unroll 8
        for (int r = 0; r < 2 * F_OUT; r++)
            s += a[r * (2 * F_OUT) + c];
        g_asum[c] = s;
    }
}

// ---------------------------------------------------------------------------
// Bucketed adjacency build: single-pass fill (degrees as side effect).
// ---------------------------------------------------------------------------
__global__ void fill_kernel(const int* __restrict__ ei, int E) {
    int e = blockIdx.x * blockDim.x + threadIdx.x;
    if (e >= E) return;
    int src = ei[e];
    int p = atomicAdd(&g_deg[src], 1);
    g_edst[src * BUCKET + p] = ei[E + e];
}

// ---------------------------------------------------------------------------
// Tensor-core GEMM via mma.sync: h = X @ W, exact bf16x3 split (6 terms).
// CTA: 256 thr (8 warps: 2m x 4n), tile 64x128, K chunks of 64, 3 CTAs/SM
// (launch_bounds caps regs at 85 so smem-permitted residency is reached).
// Epilogue also computes lin_s/lin_d per row (smem reduction).
// ---------------------------------------------------------------------------
__global__ void __launch_bounds__(256, 3)
gemm_mma_kernel(const float* __restrict__ X) {
    extern __shared__ char smem[];
    __shared__ float s_asum[2 * F_OUT];
    __shared__ float s_lin[2][GTILE_M];
    const uint32_t sb = smem_u32(smem);
    const int tid = threadIdx.x;
    const int lane = tid & 31;
    const int wid = tid >> 5;
    const int warp_m = wid & 1;
    const int warp_n = wid >> 1;
    const int block_row = blockIdx.x * GTILE_M;

    s_asum[tid] = g_asum[tid];
    if (tid < GTILE_M) { s_lin[0][tid] = 0.f; s_lin[1][tid] = 0.f; }

    float acc[2][4][4];
    #pragma unroll
    for (int mt = 0; mt < 2; mt++)
        #pragma unroll
        for (int nt = 0; nt < 4; nt++)
            #pragma unroll
            for (int j = 0; j < 4; j++) acc[mt][nt][j] = 0.f;

    for (int c = 0; c < NCHUNKS; c++) {
        __syncthreads();
        // ---- fill A: load X fp32, split to 3 bf16 tiles (swizzled [m][k]) ----
        #pragma unroll
        for (int i = 0; i < 2; i++) {
            int u = tid + i * 256;
            int row = u >> 3;
            int kseg = u & 7;
            int gr = block_row + row;
            float4 v0, v1;
            if (gr < N_NODES) {
                const float* p = X + (size_t)gr * F_IN + c * KCHUNK + kseg * 8;
                v0 = *reinterpret_cast<const float4*>(p);
                v1 = *reinterpret_cast<const float4*>(p + 4);
            } else {
                v0 = make_float4(0.f, 0.f, 0.f, 0.f);
                v1 = v0;
            }
            float vals[8] = {v0.x, v0.y, v0.z, v0.w, v1.x, v1.y, v1.z, v1.w};
            uint32_t w0[4], w1[4], w2[4];
            #pragma unroll
            for (int j = 0; j < 4; j++) {
                uint32_t l0, l1, l2, h0, h1, h2;
                split3(vals[2 * j], l0, l1, l2);
                split3(vals[2 * j + 1], h0, h1, h2);
                w0[j] = l0 | (h0 << 16);
                w1[j] = l1 | (h1 << 16);
                w2[j] = l2 | (h2 << 16);
            }
            uint32_t off = (uint32_t)(row * 128) + (uint32_t)((kseg ^ (row & 7)) << 4);
            *reinterpret_cast<uint4*>(smem + A_OFF(0) + off) = make_uint4(w0[0], w0[1], w0[2], w0[3]);
            *reinterpret_cast<uint4*>(smem + A_OFF(1) + off) = make_uint4(w1[0], w1[1], w1[2], w1[3]);
            *reinterpret_cast<uint4*>(smem + A_OFF(2) + off) = make_uint4(w2[0], w2[1], w2[2], w2[3]);
        }
        // ---- fill B: pre-split bf16 from g_wb (swizzled [n][k]) ----
        #pragma unroll
        for (int i = 0; i < 12; i++) {
            int u = tid + i * 256;
            int s = u >> 10;
            int rem = u & 1023;
            int n = rem >> 3;
            int kseg = rem & 7;
            uint4 v = *reinterpret_cast<const uint4*>(
                g_wb + s * WSSTRIDE + ((c * F_OUT + n) * KCHUNK + kseg * 8));
            uint32_t off = (uint32_t)(n * 128) + (uint32_t)((kseg ^ (n & 7)) << 4);
            *reinterpret_cast<uint4*>(smem + B_OFF(s) + off) = v;
        }
        __syncthreads();

        // ---- compute: A-split sa pairs with B-splits 0..(2-sa) ----
        #pragma unroll
        for (int sa = 0; sa < 3; sa++) {
            const int nb = 3 - sa;
            const uint32_t abase = sb + A_OFF(sa);
            #pragma unroll
            for (int ks = 0; ks < 4; ks++) {
                uint32_t afr[2][4];
                #pragma unroll
                for (int mt = 0; mt < 2; mt++) {
                    int row = warp_m * 32 + mt * 16 + (lane & 15);
                    int kseg = ks * 2 + (lane >> 4);
                    ldsm4(afr[mt], abase + row * 128 + ((kseg ^ (row & 7)) << 4));
                }
                for (int sbi = 0; sbi < nb; sbi++) {
                    const uint32_t bbase = sb + B_OFF(sbi);
                    uint32_t bfr[2][4];
                    #pragma unroll
                    for (int np = 0; np < 2; np++) {
                        int n = warp_n * 32 + np * 16 + ((lane & 7) | ((lane >> 4) << 3));
                        int kseg = ks * 2 + ((lane >> 3) & 1);
                        ldsm4(bfr[np], bbase + n * 128 + ((kseg ^ (n & 7)) << 4));
                    }
                    #pragma unroll
                    for (int mt = 0; mt < 2; mt++)
                        #pragma unroll
                        for (int nt = 0; nt < 4; nt++)
                            mma16816(acc[mt][nt], afr[mt], &bfr[nt >> 1][(nt & 1) * 2]);
                }
            }
        }
    }

    // ---- epilogue: write h + lin partials ----
    #pragma unroll
    for (int mt = 0; mt < 2; mt++) {
        float ps0 = 0.f, pd0 = 0.f, ps1 = 0.f, pd1 = 0.f;
        #pragma unroll
        for (int nt = 0; nt < 4; nt++) {
            int row = block_row + warp_m * 32 + mt * 16 + (lane >> 2);
            int col = warp_n * 32 + nt * 8 + (lane & 3) * 2;
            float a1x = s_asum[col],         a1y = s_asum[col + 1];
            float a2x = s_asum[F_OUT + col], a2y = s_asum[F_OUT + col + 1];
            ps0 += acc[mt][nt][0] * a1x + acc[mt][nt][1] * a1y;
            pd0 += acc[mt][nt][0] * a2x + acc[mt][nt][1] * a2y;
            ps1 += acc[mt][nt][2] * a1x + acc[mt][nt][3] * a1y;
            pd1 += acc[mt][nt][2] * a2x + acc[mt][nt][3] * a2y;
            if (row < N_NODES)
                *reinterpret_cast<float2*>(&g_h[(size_t)row * F_OUT + col]) =
                    make_float2(acc[mt][nt][0], acc[mt][nt][1]);
            if (row + 8 < N_NODES)
                *reinterpret_cast<float2*>(&g_h[(size_t)(row + 8) * F_OUT + col]) =
                    make_float2(acc[mt][nt][2], acc[mt][nt][3]);
        }
        // reduce across the 4 lanes sharing a row (lane&3)
        #pragma unroll
        for (int o = 1; o <= 2; o <<= 1) {
            ps0 += __shfl_xor_sync(0xFFFFFFFFu, ps0, o);
            pd0 += __shfl_xor_sync(0xFFFFFFFFu, pd0, o);
            ps1 += __shfl_xor_sync(0xFFFFFFFFu, ps1, o);
            pd1 += __shfl_xor_sync(0xFFFFFFFFu, pd1, o);
        }
        if ((lane & 3) == 0) {
            int r0 = warp_m * 32 + mt * 16 + (lane >> 2);
            atomicAdd(&s_lin[0][r0], ps0);
            atomicAdd(&s_lin[1][r0], pd0);
            atomicAdd(&s_lin[0][r0 + 8], ps1);
            atomicAdd(&s_lin[1][r0 + 8], pd1);
        }
    }
    __syncthreads();
    if (tid < GTILE_M && block_row + tid < N_NODES) {
        g_lin_s[block_row + tid] = s_lin[0][tid];
        g_lin_d[block_row + tid] = s_lin[1][tid];
    }
}

// ---------------------------------------------------------------------------
// Node kernel: one warp per node; 4 groups of 8 lanes, each group one
// neighbor at a time (16 LDG.128 in flight per warp). Register accumulation,
// zero atomics, fused divide+ELU output. Bucketed adjacency.
// (Byte-identical to R11's measured best: 64 regs, protected.)
// ---------------------------------------------------------------------------
__global__ void __launch_bounds__(256) node_kernel(float* __restrict__ out) {
    int node = (blockIdx.x * blockDim.x + threadIdx.x) >> 5;
    int lane = threadIdx.x & 31;
    if (node >= N_NODES) return;
    int sub = lane & 7;     // feature sub-chunk: floats q*32 + sub*4
    int grp = lane >> 3;    // neighbor group 0..3

    const int start = node * BUCKET;
    const int cnt   = g_deg[node];
    const float* hrow = &g_h[(size_t)node * F_OUT];

    float4 hs[4], acc[4];
    #pragma unroll
    for (int q = 0; q < 4; q++) {
        hs[q] = *reinterpret_cast<const float4*>(hrow + q * 32 + sub * 4);
        acc[q] = make_float4(0.f, 0.f, 0.f, 0.f);
    }
    const float lins = g_lin_s[node];
    float rs = 0.f;

    for (int j = 0; j < cnt; j += 4) {
        int mye = j + grp;
        bool valid = (mye < cnt);
        int dst = valid ? g_edst[start + mye] : 0;
        const float* hdp = &g_h[(size_t)dst * F_OUT];
        float4 hd[4];
        #pragma unroll
        for (int q = 0; q < 4; q++)
            hd[q] = *reinterpret_cast<const float4*>(hdp + q * 32 + sub * 4);

        float c = 0.f;
        #pragma unroll
        for (int q = 0; q < 4; q++)
            c += hs[q].x * hd[q].x + hs[q].y * hd[q].y + hs[q].z * hd[q].z + hs[q].w * hd[q].w;
        c += __shfl_xor_sync(0xFFFFFFFFu, c, 1);
        c += __shfl_xor_sync(0xFFFFFFFFu, c, 2);
        c += __shfl_xor_sync(0xFFFFFFFFu, c, 4);

        float lin = lins + g_lin_d[dst];
        float sig = __fdividef(1.f, 1.f + __expf(-c));
        float z = lin * sig;
        float lr = (z >= 0.f) ? z : ALPHA * z;
        float e = valid ? __expf(-lr) : 0.f;

        #pragma unroll
        for (int q = 0; q < 4; q++) {
            acc[q].x += e * hd[q].x;
            acc[q].y += e * hd[q].y;
            acc[q].z += e * hd[q].z;
            acc[q].w += e * hd[q].w;
        }
        rs += e;
    }

    // reduce across the 4 neighbor-groups (lanes sub, sub+8, sub+16, sub+24)
    #pragma unroll
    for (int o = 8; o <= 16; o <<= 1) {
        #pragma unroll
        for (int q = 0; q < 4; q++) {
            acc[q].x += __shfl_xor_sync(0xFFFFFFFFu, acc[q].x, o);
            acc[q].y += __shfl_xor_sync(0xFFFFFFFFu, acc[q].y, o);
            acc[q].z += __shfl_xor_sync(0xFFFFFFFFu, acc[q].z, o);
            acc[q].w += __shfl_xor_sync(0xFFFFFFFFu, acc[q].w, o);
        }
        rs += __shfl_xor_sync(0xFFFFFFFFu, rs, o);
    }

    if (grp == 0) {
        float inv = __fdividef(1.f, rs + 1e-8f);
        #pragma unroll
        for (int q = 0; q < 4; q++) {
            float4 v = make_float4(acc[q].x * inv, acc[q].y * inv,
                                   acc[q].z * inv, acc[q].w * inv);
            v.x = (v.x > 0.f) ? v.x : expm1f(v.x);
            v.y = (v.y > 0.f) ? v.y : expm1f(v.y);
            v.z = (v.z > 0.f) ? v.z : expm1f(v.z);
            v.w = (v.w > 0.f) ? v.w : expm1f(v.w);
            *reinterpret_cast<float4*>(&out[(size_t)node * F_OUT + q * 32 + sub * 4]) = v;
        }
    }
}

// ---------------------------------------------------------------------------
extern "C" void kernel_launch(void* const* d_in, const int* in_sizes, int n_in,
                              void* d_out, int out_size) {
    const float* x  = (const float*)d_in[0];
    const int*   ei = (const int*)d_in[1];
    const float* W  = (const float*)d_in[2];
    const float* a  = (const float*)d_in[3];
    float* out = (float*)d_out;

    const int E = in_sizes[1] / 2;

    cudaFuncSetAttribute(gemm_mma_kernel,
                         cudaFuncAttributeMaxDynamicSharedMemorySize, SMEM_TOTAL);

    setup_kernel<<<ZBLK + WBLK + 1, 256>>>(W, a);
    fill_kernel<<<(E + 255) / 256, 256>>>(ei, E);
    gemm_mma_kernel<<<NTILES, 256, SMEM_TOTAL>>>(x);
    node_kernel<<<(N_NODES * 32 + 255) / 256, 256>>>(out);
}

// round 14
// speedup vs baseline: 1.3143x; 1.3143x over previous
#include <cuda_runtime.h>
#include <math.h>
#include <stdint.h>

#define N_NODES 50000
#define E_MAX   800000
#define F_IN    256
#define F_OUT   128
#define ALPHA   0.2f
#define BUCKET  64          // slots per node; mean deg 16, sigma 4 -> 12-sigma margin

#define GTILE_M 64
#define KCHUNK  64
#define NCHUNKS (F_IN / KCHUNK)                       // 4
#define NTILES  ((N_NODES + GTILE_M - 1) / GTILE_M)   // 782
#define WSSTRIDE (NCHUNKS * F_OUT * KCHUNK)           // 32768

// smem: 3 A-split tiles (64x128B = 8KB) + 3 B-split tiles (128x128B = 16KB)
#define ATILEB  8192
#define BTILEB  16384
#define A_OFF(s) ((s) * ATILEB)
#define B_OFF(s) (3 * ATILEB + (s) * BTILEB)
#define SMEM_TOTAL (3 * ATILEB + 3 * BTILEB)          // 73728

// setup kernel grid split
#define ZBLK ((N_NODES + 255) / 256)                  // 196
#define WBLK ((F_IN * F_OUT + 255) / 256)             // 128

// Scratch (__device__ globals: allocation-free)
__device__ float g_h[N_NODES * F_OUT];
__device__ float g_lin_s[N_NODES];
__device__ float g_lin_d[N_NODES];
__device__ float g_asum[2 * F_OUT];
__device__ unsigned short g_wb[3 * WSSTRIDE];   // [split][chunk][n][kk]
__device__ int g_deg[N_NODES];
__device__ int g_edst[N_NODES * BUCKET];        // bucketed adjacency

// ---------------------------------------------------------------------------
__device__ __forceinline__ uint32_t smem_u32(const void* p) {
    uint32_t a;
    asm("{ .reg .u64 t; cvta.to.shared.u64 t, %1; cvt.u32.u64 %0, t; }"
        : "=r"(a) : "l"(p));
    return a;
}

__device__ __forceinline__ void ldsm4(uint32_t* r, uint32_t addr) {
    asm volatile("ldmatrix.sync.aligned.m8n8.x4.shared.b16 {%0,%1,%2,%3}, [%4];"
                 : "=r"(r[0]), "=r"(r[1]), "=r"(r[2]), "=r"(r[3]) : "r"(addr));
}

__device__ __forceinline__ void mma16816(float* d, const uint32_t* a, const uint32_t* b) {
    asm volatile(
        "mma.sync.aligned.m16n8k16.row.col.f32.bf16.bf16.f32 "
        "{%0,%1,%2,%3},{%4,%5,%6,%7},{%8,%9},{%0,%1,%2,%3};"
        : "+f"(d[0]), "+f"(d[1]), "+f"(d[2]), "+f"(d[3])
        : "r"(a[0]), "r"(a[1]), "r"(a[2]), "r"(a[3]), "r"(b[0]), "r"(b[1]));
}

// exact 3-way bf16 truncation split: v == b0 + b1 + b2 (+ ~2^-24 residual)
__device__ __forceinline__ void split3(float v, uint32_t& b0, uint32_t& b1, uint32_t& b2) {
    uint32_t u = __float_as_uint(v);
    b0 = u >> 16;
    float r1 = v - __uint_as_float(u & 0xFFFF0000u);
    uint32_t u1 = __float_as_uint(r1);
    b1 = u1 >> 16;
    float r2 = r1 - __uint_as_float(u1 & 0xFFFF0000u);
    b2 = __float_as_uint(r2) >> 16;
}

// ---------------------------------------------------------------------------
// Setup: zero degrees | split W | asum  (independent work, one launch)
// ---------------------------------------------------------------------------
__global__ void setup_kernel(const float* __restrict__ W,
                             const float* __restrict__ a) {
    int bid = blockIdx.x;
    if (bid < ZBLK) {
        int i = bid * 256 + threadIdx.x;
        if (i < N_NODES) g_deg[i] = 0;
    } else if (bid < ZBLK + WBLK) {
        int i = (bid - ZBLK) * 256 + threadIdx.x;
        if (i < F_IN * F_OUT) {
            int k = i >> 7, n = i & 127;
            uint32_t b0, b1, b2;
            split3(W[i], b0, b1, b2);
            int base = ((k >> 6) * F_OUT + n) * KCHUNK + (k & 63);
            g_wb[base]                = (unsigned short)b0;
            g_wb[WSSTRIDE + base]     = (unsigned short)b1;
            g_wb[2 * WSSTRIDE + base] = (unsigned short)b2;
        }
    } else {
        int c = threadIdx.x;
        float s = 0.f;
        #pragma unroll 8
        for (int r = 0; r < 2 * F_OUT; r++)
            s += a[r * (2 * F_OUT) + c];
        g_asum[c] = s;
    }
}

// ---------------------------------------------------------------------------
// Bucketed adjacency build: single-pass fill (degrees as side effect).
// ---------------------------------------------------------------------------
__global__ void fill_kernel(const int* __restrict__ ei, int E) {
    int e = blockIdx.x * blockDim.x + threadIdx.x;
    if (e >= E) return;
    int src = ei[e];
    int p = atomicAdd(&g_deg[src], 1);
    g_edst[src * BUCKET + p] = ei[E + e];
}

// ---------------------------------------------------------------------------
// Tensor-core GEMM via mma.sync: h = X @ W, exact bf16x3 split (6 terms).
// CTA: 256 thr (8 warps: 2m x 4n), tile 64x128, K chunks of 64, 2 CTAs/SM.
// Epilogue also computes lin_s/lin_d per row (smem reduction).
// (Byte-identical to R11's measured best.)
// ---------------------------------------------------------------------------
__global__ void __launch_bounds__(256, 2)
gemm_mma_kernel(const float* __restrict__ X) {
    extern __shared__ char smem[];
    __shared__ float s_asum[2 * F_OUT];
    __shared__ float s_lin[2][GTILE_M];
    const uint32_t sb = smem_u32(smem);
    const int tid = threadIdx.x;
    const int lane = tid & 31;
    const int wid = tid >> 5;
    const int warp_m = wid & 1;
    const int warp_n = wid >> 1;
    const int block_row = blockIdx.x * GTILE_M;

    s_asum[tid] = g_asum[tid];
    if (tid < GTILE_M) { s_lin[0][tid] = 0.f; s_lin[1][tid] = 0.f; }

    float acc[2][4][4];
    #pragma unroll
    for (int mt = 0; mt < 2; mt++)
        #pragma unroll
        for (int nt = 0; nt < 4; nt++)
            #pragma unroll
            for (int j = 0; j < 4; j++) acc[mt][nt][j] = 0.f;

    for (int c = 0; c < NCHUNKS; c++) {
        __syncthreads();
        // ---- fill A: load X fp32, split to 3 bf16 tiles (swizzled [m][k]) ----
        #pragma unroll
        for (int i = 0; i < 2; i++) {
            int u = tid + i * 256;
            int row = u >> 3;
            int kseg = u & 7;
            int gr = block_row + row;
            float4 v0, v1;
            if (gr < N_NODES) {
                const float* p = X + (size_t)gr * F_IN + c * KCHUNK + kseg * 8;
                v0 = *reinterpret_cast<const float4*>(p);
                v1 = *reinterpret_cast<const float4*>(p + 4);
            } else {
                v0 = make_float4(0.f, 0.f, 0.f, 0.f);
                v1 = v0;
            }
            float vals[8] = {v0.x, v0.y, v0.z, v0.w, v1.x, v1.y, v1.z, v1.w};
            uint32_t w0[4], w1[4], w2[4];
            #pragma unroll
            for (int j = 0; j < 4; j++) {
                uint32_t l0, l1, l2, h0, h1, h2;
                split3(vals[2 * j], l0, l1, l2);
                split3(vals[2 * j + 1], h0, h1, h2);
                w0[j] = l0 | (h0 << 16);
                w1[j] = l1 | (h1 << 16);
                w2[j] = l2 | (h2 << 16);
            }
            uint32_t off = (uint32_t)(row * 128) + (uint32_t)((kseg ^ (row & 7)) << 4);
            *reinterpret_cast<uint4*>(smem + A_OFF(0) + off) = make_uint4(w0[0], w0[1], w0[2], w0[3]);
            *reinterpret_cast<uint4*>(smem + A_OFF(1) + off) = make_uint4(w1[0], w1[1], w1[2], w1[3]);
            *reinterpret_cast<uint4*>(smem + A_OFF(2) + off) = make_uint4(w2[0], w2[1], w2[2], w2[3]);
        }
        // ---- fill B: pre-split bf16 from g_wb (swizzled [n][k]) ----
        #pragma unroll
        for (int i = 0; i < 12; i++) {
            int u = tid + i * 256;
            int s = u >> 10;
            int rem = u & 1023;
            int n = rem >> 3;
            int kseg = rem & 7;
            uint4 v = *reinterpret_cast<const uint4*>(
                g_wb + s * WSSTRIDE + ((c * F_OUT + n) * KCHUNK + kseg * 8));
            uint32_t off = (uint32_t)(n * 128) + (uint32_t)((kseg ^ (n & 7)) << 4);
            *reinterpret_cast<uint4*>(smem + B_OFF(s) + off) = v;
        }
        __syncthreads();

        // ---- compute: A-split sa pairs with B-splits 0..(2-sa) ----
        #pragma unroll
        for (int sa = 0; sa < 3; sa++) {
            const int nb = 3 - sa;
            const uint32_t abase = sb + A_OFF(sa);
            #pragma unroll
            for (int ks = 0; ks < 4; ks++) {
                uint32_t afr[2][4];
                #pragma unroll
                for (int mt = 0; mt < 2; mt++) {
                    int row = warp_m * 32 + mt * 16 + (lane & 15);
                    int kseg = ks * 2 + (lane >> 4);
                    ldsm4(afr[mt], abase + row * 128 + ((kseg ^ (row & 7)) << 4));
                }
                for (int sbi = 0; sbi < nb; sbi++) {
                    const uint32_t bbase = sb + B_OFF(sbi);
                    uint32_t bfr[2][4];
                    #pragma unroll
                    for (int np = 0; np < 2; np++) {
                        int n = warp_n * 32 + np * 16 + ((lane & 7) | ((lane >> 4) << 3));
                        int kseg = ks * 2 + ((lane >> 3) & 1);
                        ldsm4(bfr[np], bbase + n * 128 + ((kseg ^ (n & 7)) << 4));
                    }
                    #pragma unroll
                    for (int mt = 0; mt < 2; mt++)
                        #pragma unroll
                        for (int nt = 0; nt < 4; nt++)
                            mma16816(acc[mt][nt], afr[mt], &bfr[nt >> 1][(nt & 1) * 2]);
                }
            }
        }
    }

    // ---- epilogue: write h + lin partials ----
    #pragma unroll
    for (int mt = 0; mt < 2; mt++) {
        float ps0 = 0.f, pd0 = 0.f, ps1 = 0.f, pd1 = 0.f;
        #pragma unroll
        for (int nt = 0; nt < 4; nt++) {
            int row = block_row + warp_m * 32 + mt * 16 + (lane >> 2);
            int col = warp_n * 32 + nt * 8 + (lane & 3) * 2;
            float a1x = s_asum[col],         a1y = s_asum[col + 1];
            float a2x = s_asum[F_OUT + col], a2y = s_asum[F_OUT + col + 1];
            ps0 += acc[mt][nt][0] * a1x + acc[mt][nt][1] * a1y;
            pd0 += acc[mt][nt][0] * a2x + acc[mt][nt][1] * a2y;
            ps1 += acc[mt][nt][2] * a1x + acc[mt][nt][3] * a1y;
            pd1 += acc[mt][nt][2] * a2x + acc[mt][nt][3] * a2y;
            if (row < N_NODES)
                *reinterpret_cast<float2*>(&g_h[(size_t)row * F_OUT + col]) =
                    make_float2(acc[mt][nt][0], acc[mt][nt][1]);
            if (row + 8 < N_NODES)
                *reinterpret_cast<float2*>(&g_h[(size_t)(row + 8) * F_OUT + col]) =
                    make_float2(acc[mt][nt][2], acc[mt][nt][3]);
        }
        // reduce across the 4 lanes sharing a row (lane&3)
        #pragma unroll
        for (int o = 1; o <= 2; o <<= 1) {
            ps0 += __shfl_xor_sync(0xFFFFFFFFu, ps0, o);
            pd0 += __shfl_xor_sync(0xFFFFFFFFu, pd0, o);
            ps1 += __shfl_xor_sync(0xFFFFFFFFu, ps1, o);
            pd1 += __shfl_xor_sync(0xFFFFFFFFu, pd1, o);
        }
        if ((lane & 3) == 0) {
            int r0 = warp_m * 32 + mt * 16 + (lane >> 2);
            atomicAdd(&s_lin[0][r0], ps0);
            atomicAdd(&s_lin[1][r0], pd0);
            atomicAdd(&s_lin[0][r0 + 8], ps1);
            atomicAdd(&s_lin[1][r0 + 8], pd1);
        }
    }
    __syncthreads();
    if (tid < GTILE_M && block_row + tid < N_NODES) {
        g_lin_s[block_row + tid] = s_lin[0][tid];
        g_lin_d[block_row + tid] = s_lin[1][tid];
    }
}

// ---------------------------------------------------------------------------
// Node kernel: ONE WARP = ONE CTA (fine-grained retirement; registers free
// per node instead of per 8-node block). Body identical to R11's protected
// version: 4 groups of 8 lanes, 16 LDG.128 in flight, zero atomics,
// fused divide+ELU.
// ---------------------------------------------------------------------------
__global__ void __launch_bounds__(32) node_kernel(float* __restrict__ out) {
    int node = blockIdx.x;
    int lane = threadIdx.x;
    int sub = lane & 7;     // feature sub-chunk: floats q*32 + sub*4
    int grp = lane >> 3;    // neighbor group 0..3

    const int start = node * BUCKET;
    const int cnt   = g_deg[node];
    const float* hrow = &g_h[(size_t)node * F_OUT];

    float4 hs[4], acc[4];
    #pragma unroll
    for (int q = 0; q < 4; q++) {
        hs[q] = *reinterpret_cast<const float4*>(hrow + q * 32 + sub * 4);
        acc[q] = make_float4(0.f, 0.f, 0.f, 0.f);
    }
    const float lins = g_lin_s[node];
    float rs = 0.f;

    for (int j = 0; j < cnt; j += 4) {
        int mye = j + grp;
        bool valid = (mye < cnt);
        int dst = valid ? g_edst[start + mye] : 0;
        const float* hdp = &g_h[(size_t)dst * F_OUT];
        float4 hd[4];
        #pragma unroll
        for (int q = 0; q < 4; q++)
            hd[q] = *reinterpret_cast<const float4*>(hdp + q * 32 + sub * 4);

        float c = 0.f;
        #pragma unroll
        for (int q = 0; q < 4; q++)
            c += hs[q].x * hd[q].x + hs[q].y * hd[q].y + hs[q].z * hd[q].z + hs[q].w * hd[q].w;
        c += __shfl_xor_sync(0xFFFFFFFFu, c, 1);
        c += __shfl_xor_sync(0xFFFFFFFFu, c, 2);
        c += __shfl_xor_sync(0xFFFFFFFFu, c, 4);

        float lin = lins + g_lin_d[dst];
        float sig = __fdividef(1.f, 1.f + __expf(-c));
        float z = lin * sig;
        float lr = (z >= 0.f) ? z : ALPHA * z;
        float e = valid ? __expf(-lr) : 0.f;

        #pragma unroll
        for (int q = 0; q < 4; q++) {
            acc[q].x += e * hd[q].x;
            acc[q].y += e * hd[q].y;
            acc[q].z += e * hd[q].z;
            acc[q].w += e * hd[q].w;
        }
        rs += e;
    }

    // reduce across the 4 neighbor-groups (lanes sub, sub+8, sub+16, sub+24)
    #pragma unroll
    for (int o = 8; o <= 16; o <<= 1) {
        #pragma unroll
        for (int q = 0; q < 4; q++) {
            acc[q].x += __shfl_xor_sync(0xFFFFFFFFu, acc[q].x, o);
            acc[q].y += __shfl_xor_sync(0xFFFFFFFFu, acc[q].y, o);
            acc[q].z += __shfl_xor_sync(0xFFFFFFFFu, acc[q].z, o);
            acc[q].w += __shfl_xor_sync(0xFFFFFFFFu, acc[q].w, o);
        }
        rs += __shfl_xor_sync(0xFFFFFFFFu, rs, o);
    }

    if (grp == 0) {
        float inv = __fdividef(1.f, rs + 1e-8f);
        #pragma unroll
        for (int q = 0; q < 4; q++) {
            float4 v = make_float4(acc[q].x * inv, acc[q].y * inv,
                                   acc[q].z * inv, acc[q].w * inv);
            v.x = (v.x > 0.f) ? v.x : expm1f(v.x);
            v.y = (v.y > 0.f) ? v.y : expm1f(v.y);
            v.z = (v.z > 0.f) ? v.z : expm1f(v.z);
            v.w = (v.w > 0.f) ? v.w : expm1f(v.w);
            *reinterpret_cast<float4*>(&out[(size_t)node * F_OUT + q * 32 + sub * 4]) = v;
        }
    }
}

// ---------------------------------------------------------------------------
extern "C" void kernel_launch(void* const* d_in, const int* in_sizes, int n_in,
                              void* d_out, int out_size) {
    const float* x  = (const float*)d_in[0];
    const int*   ei = (const int*)d_in[1];
    const float* W  = (const float*)d_in[2];
    const float* a  = (const float*)d_in[3];
    float* out = (float*)d_out;

    const int E = in_sizes[1] / 2;

    cudaFuncSetAttribute(gemm_mma_kernel,
                         cudaFuncAttributeMaxDynamicSharedMemorySize, SMEM_TOTAL);

    setup_kernel<<<ZBLK + WBLK + 1, 256>>>(W, a);
    fill_kernel<<<(E + 255) / 256, 256>>>(ei, E);
    gemm_mma_kernel<<<NTILES, 256, SMEM_TOTAL>>>(x);
    node_kernel<<<N_NODES, 32>>>(out);
}

// round 15
// speedup vs baseline: 1.3899x; 1.0575x over previous
#include <cuda_runtime.h>
#include <math.h>
#include <stdint.h>

#define N_NODES 50000
#define E_MAX   800000
#define F_IN    256
#define F_OUT   128
#define ALPHA   0.2f
#define BUCKET  64          // slots per node; mean deg 16, sigma 4 -> 12-sigma margin

#define GTILE_M 64
#define KCHUNK  64
#define NCHUNKS (F_IN / KCHUNK)                       // 4
#define NTILES  ((N_NODES + GTILE_M - 1) / GTILE_M)   // 782
#define WSSTRIDE (NCHUNKS * F_OUT * KCHUNK)           // 32768
#define FBLK    ((E_MAX + 255) / 256)                 // 3125 fill blocks

// smem: 3 A-split tiles (64x128B = 8KB) + 3 B-split tiles (128x128B = 16KB)
#define ATILEB  8192
#define BTILEB  16384
#define A_OFF(s) ((s) * ATILEB)
#define B_OFF(s) (3 * ATILEB + (s) * BTILEB)
#define SMEM_TOTAL (3 * ATILEB + 3 * BTILEB)          // 73728

// setup kernel grid split
#define ZBLK ((N_NODES + 255) / 256)                  // 196
#define WBLK ((F_IN * F_OUT + 255) / 256)             // 128

// Scratch (__device__ globals: allocation-free)
__device__ float g_h[N_NODES * F_OUT];
__device__ float g_lin_s[N_NODES];
__device__ float g_lin_d[N_NODES];
__device__ float g_asum[2 * F_OUT];
__device__ unsigned short g_wb[3 * WSSTRIDE];   // [split][chunk][n][kk]
__device__ int g_deg[N_NODES];
__device__ int g_edst[N_NODES * BUCKET];        // bucketed adjacency

// ---------------------------------------------------------------------------
__device__ __forceinline__ uint32_t smem_u32(const void* p) {
    uint32_t a;
    asm("{ .reg .u64 t; cvta.to.shared.u64 t, %1; cvt.u32.u64 %0, t; }"
        : "=r"(a) : "l"(p));
    return a;
}

__device__ __forceinline__ void ldsm4(uint32_t* r, uint32_t addr) {
    asm volatile("ldmatrix.sync.aligned.m8n8.x4.shared.b16 {%0,%1,%2,%3}, [%4];"
                 : "=r"(r[0]), "=r"(r[1]), "=r"(r[2]), "=r"(r[3]) : "r"(addr));
}

__device__ __forceinline__ void mma16816(float* d, const uint32_t* a, const uint32_t* b) {
    asm volatile(
        "mma.sync.aligned.m16n8k16.row.col.f32.bf16.bf16.f32 "
        "{%0,%1,%2,%3},{%4,%5,%6,%7},{%8,%9},{%0,%1,%2,%3};"
        : "+f"(d[0]), "+f"(d[1]), "+f"(d[2]), "+f"(d[3])
        : "r"(a[0]), "r"(a[1]), "r"(a[2]), "r"(a[3]), "r"(b[0]), "r"(b[1]));
}

// exact 3-way bf16 truncation split: v == b0 + b1 + b2 (+ ~2^-24 residual)
__device__ __forceinline__ void split3(float v, uint32_t& b0, uint32_t& b1, uint32_t& b2) {
    uint32_t u = __float_as_uint(v);
    b0 = u >> 16;
    float r1 = v - __uint_as_float(u & 0xFFFF0000u);
    uint32_t u1 = __float_as_uint(r1);
    b1 = u1 >> 16;
    float r2 = r1 - __uint_as_float(u1 & 0xFFFF0000u);
    b2 = __float_as_uint(r2) >> 16;
}

// ---------------------------------------------------------------------------
// Setup: zero degrees | split W | asum  (independent work, one launch)
// ---------------------------------------------------------------------------
__global__ void setup_kernel(const float* __restrict__ W,
                             const float* __restrict__ a) {
    int bid = blockIdx.x;
    if (bid < ZBLK) {
        int i = bid * 256 + threadIdx.x;
        if (i < N_NODES) g_deg[i] = 0;
    } else if (bid < ZBLK + WBLK) {
        int i = (bid - ZBLK) * 256 + threadIdx.x;
        if (i < F_IN * F_OUT) {
            int k = i >> 7, n = i & 127;
            uint32_t b0, b1, b2;
            split3(W[i], b0, b1, b2);
            int base = ((k >> 6) * F_OUT + n) * KCHUNK + (k & 63);
            g_wb[base]                = (unsigned short)b0;
            g_wb[WSSTRIDE + base]     = (unsigned short)b1;
            g_wb[2 * WSSTRIDE + base] = (unsigned short)b2;
        }
    } else {
        int c = threadIdx.x;
        float s = 0.f;
        #pragma unroll 8
        for (int r = 0; r < 2 * F_OUT; r++)
            s += a[r * (2 * F_OUT) + c];
        g_asum[c] = s;
    }
}

// ---------------------------------------------------------------------------
// Merged GEMM + adjacency-fill kernel.
// Blocks [0, NTILES): tensor-core GEMM (h = X @ W via exact bf16x3 split,
//   6 terms, 64x128 tile, epilogue computes lin_s/lin_d).
// Blocks [NTILES, NTILES+FBLK): bucketed adjacency fill (independent work,
//   runs concurrently in scheduling gaps of the GEMM waves).
// ---------------------------------------------------------------------------
__global__ void __launch_bounds__(256, 2)
gemm_fill_kernel(const float* __restrict__ X, const int* __restrict__ ei, int E) {
    if (blockIdx.x >= NTILES) {
        // ---------------- fill branch ----------------
        int e = (blockIdx.x - NTILES) * 256 + threadIdx.x;
        if (e < E) {
            int src = ei[e];
            int p = atomicAdd(&g_deg[src], 1);
            g_edst[src * BUCKET + p] = ei[E + e];
        }
        return;
    }

    // ---------------- GEMM branch (byte-identical logic to R11 best) ----------------
    extern __shared__ char smem[];
    __shared__ float s_asum[2 * F_OUT];
    __shared__ float s_lin[2][GTILE_M];
    const uint32_t sb = smem_u32(smem);
    const int tid = threadIdx.x;
    const int lane = tid & 31;
    const int wid = tid >> 5;
    const int warp_m = wid & 1;
    const int warp_n = wid >> 1;
    const int block_row = blockIdx.x * GTILE_M;

    s_asum[tid] = g_asum[tid];
    if (tid < GTILE_M) { s_lin[0][tid] = 0.f; s_lin[1][tid] = 0.f; }

    float acc[2][4][4];
    #pragma unroll
    for (int mt = 0; mt < 2; mt++)
        #pragma unroll
        for (int nt = 0; nt < 4; nt++)
            #pragma unroll
            for (int j = 0; j < 4; j++) acc[mt][nt][j] = 0.f;

    for (int c = 0; c < NCHUNKS; c++) {
        __syncthreads();
        // ---- fill A: load X fp32, split to 3 bf16 tiles (swizzled [m][k]) ----
        #pragma unroll
        for (int i = 0; i < 2; i++) {
            int u = tid + i * 256;
            int row = u >> 3;
            int kseg = u & 7;
            int gr = block_row + row;
            float4 v0, v1;
            if (gr < N_NODES) {
                const float* p = X + (size_t)gr * F_IN + c * KCHUNK + kseg * 8;
                v0 = *reinterpret_cast<const float4*>(p);
                v1 = *reinterpret_cast<const float4*>(p + 4);
            } else {
                v0 = make_float4(0.f, 0.f, 0.f, 0.f);
                v1 = v0;
            }
            float vals[8] = {v0.x, v0.y, v0.z, v0.w, v1.x, v1.y, v1.z, v1.w};
            uint32_t w0[4], w1[4], w2[4];
            #pragma unroll
            for (int j = 0; j < 4; j++) {
                uint32_t l0, l1, l2, h0, h1, h2;
                split3(vals[2 * j], l0, l1, l2);
                split3(vals[2 * j + 1], h0, h1, h2);
                w0[j] = l0 | (h0 << 16);
                w1[j] = l1 | (h1 << 16);
                w2[j] = l2 | (h2 << 16);
            }
            uint32_t off = (uint32_t)(row * 128) + (uint32_t)((kseg ^ (row & 7)) << 4);
            *reinterpret_cast<uint4*>(smem + A_OFF(0) + off) = make_uint4(w0[0], w0[1], w0[2], w0[3]);
            *reinterpret_cast<uint4*>(smem + A_OFF(1) + off) = make_uint4(w1[0], w1[1], w1[2], w1[3]);
            *reinterpret_cast<uint4*>(smem + A_OFF(2) + off) = make_uint4(w2[0], w2[1], w2[2], w2[3]);
        }
        // ---- fill B: pre-split bf16 from g_wb (swizzled [n][k]) ----
        #pragma unroll
        for (int i = 0; i < 12; i++) {
            int u = tid + i * 256;
            int s = u >> 10;
            int rem = u & 1023;
            int n = rem >> 3;
            int kseg = rem & 7;
            uint4 v = *reinterpret_cast<const uint4*>(
                g_wb + s * WSSTRIDE + ((c * F_OUT + n) * KCHUNK + kseg * 8));
            uint32_t off = (uint32_t)(n * 128) + (uint32_t)((kseg ^ (n & 7)) << 4);
            *reinterpret_cast<uint4*>(smem + B_OFF(s) + off) = v;
        }
        __syncthreads();

        // ---- compute: A-split sa pairs with B-splits 0..(2-sa) ----
        #pragma unroll
        for (int sa = 0; sa < 3; sa++) {
            const int nb = 3 - sa;
            const uint32_t abase = sb + A_OFF(sa);
            #pragma unroll
            for (int ks = 0; ks < 4; ks++) {
                uint32_t afr[2][4];
                #pragma unroll
                for (int mt = 0; mt < 2; mt++) {
                    int row = warp_m * 32 + mt * 16 + (lane & 15);
                    int kseg = ks * 2 + (lane >> 4);
                    ldsm4(afr[mt], abase + row * 128 + ((kseg ^ (row & 7)) << 4));
                }
                for (int sbi = 0; sbi < nb; sbi++) {
                    const uint32_t bbase = sb + B_OFF(sbi);
                    uint32_t bfr[2][4];
                    #pragma unroll
                    for (int np = 0; np < 2; np++) {
                        int n = warp_n * 32 + np * 16 + ((lane & 7) | ((lane >> 4) << 3));
                        int kseg = ks * 2 + ((lane >> 3) & 1);
                        ldsm4(bfr[np], bbase + n * 128 + ((kseg ^ (n & 7)) << 4));
                    }
                    #pragma unroll
                    for (int mt = 0; mt < 2; mt++)
                        #pragma unroll
                        for (int nt = 0; nt < 4; nt++)
                            mma16816(acc[mt][nt], afr[mt], &bfr[nt >> 1][(nt & 1) * 2]);
                }
            }
        }
    }

    // ---- epilogue: write h + lin partials ----
    #pragma unroll
    for (int mt = 0; mt < 2; mt++) {
        float ps0 = 0.f, pd0 = 0.f, ps1 = 0.f, pd1 = 0.f;
        #pragma unroll
        for (int nt = 0; nt < 4; nt++) {
            int row = block_row + warp_m * 32 + mt * 16 + (lane >> 2);
            int col = warp_n * 32 + nt * 8 + (lane & 3) * 2;
            float a1x = s_asum[col],         a1y = s_asum[col + 1];
            float a2x = s_asum[F_OUT + col], a2y = s_asum[F_OUT + col + 1];
            ps0 += acc[mt][nt][0] * a1x + acc[mt][nt][1] * a1y;
            pd0 += acc[mt][nt][0] * a2x + acc[mt][nt][1] * a2y;
            ps1 += acc[mt][nt][2] * a1x + acc[mt][nt][3] * a1y;
            pd1 += acc[mt][nt][2] * a2x + acc[mt][nt][3] * a2y;
            if (row < N_NODES)
                *reinterpret_cast<float2*>(&g_h[(size_t)row * F_OUT + col]) =
                    make_float2(acc[mt][nt][0], acc[mt][nt][1]);
            if (row + 8 < N_NODES)
                *reinterpret_cast<float2*>(&g_h[(size_t)(row + 8) * F_OUT + col]) =
                    make_float2(acc[mt][nt][2], acc[mt][nt][3]);
        }
        // reduce across the 4 lanes sharing a row (lane&3)
        #pragma unroll
        for (int o = 1; o <= 2; o <<= 1) {
            ps0 += __shfl_xor_sync(0xFFFFFFFFu, ps0, o);
            pd0 += __shfl_xor_sync(0xFFFFFFFFu, pd0, o);
            ps1 += __shfl_xor_sync(0xFFFFFFFFu, ps1, o);
            pd1 += __shfl_xor_sync(0xFFFFFFFFu, pd1, o);
        }
        if ((lane & 3) == 0) {
            int r0 = warp_m * 32 + mt * 16 + (lane >> 2);
            atomicAdd(&s_lin[0][r0], ps0);
            atomicAdd(&s_lin[1][r0], pd0);
            atomicAdd(&s_lin[0][r0 + 8], ps1);
            atomicAdd(&s_lin[1][r0 + 8], pd1);
        }
    }
    __syncthreads();
    if (tid < GTILE_M && block_row + tid < N_NODES) {
        g_lin_s[block_row + tid] = s_lin[0][tid];
        g_lin_d[block_row + tid] = s_lin[1][tid];
    }
}

// ---------------------------------------------------------------------------
// Node kernel: ONE WARP = ONE CTA (fine-grained retirement). Body identical
// to R11/R14 protected version: 4 groups of 8 lanes, 16 LDG.128 in flight,
// zero atomics, fused divide+ELU.
// ---------------------------------------------------------------------------
__global__ void __launch_bounds__(32) node_kernel(float* __restrict__ out) {
    int node = blockIdx.x;
    int lane = threadIdx.x;
    int sub = lane & 7;     // feature sub-chunk: floats q*32 + sub*4
    int grp = lane >> 3;    // neighbor group 0..3

    const int start = node * BUCKET;
    const int cnt   = g_deg[node];
    const float* hrow = &g_h[(size_t)node * F_OUT];

    float4 hs[4], acc[4];
    #pragma unroll
    for (int q = 0; q < 4; q++) {
        hs[q] = *reinterpret_cast<const float4*>(hrow + q * 32 + sub * 4);
        acc[q] = make_float4(0.f, 0.f, 0.f, 0.f);
    }
    const float lins = g_lin_s[node];
    float rs = 0.f;

    for (int j = 0; j < cnt; j += 4) {
        int mye = j + grp;
        bool valid = (mye < cnt);
        int dst = valid ? g_edst[start + mye] : 0;
        const float* hdp = &g_h[(size_t)dst * F_OUT];
        float4 hd[4];
        #pragma unroll
        for (int q = 0; q < 4; q++)
            hd[q] = *reinterpret_cast<const float4*>(hdp + q * 32 + sub * 4);

        float c = 0.f;
        #pragma unroll
        for (int q = 0; q < 4; q++)
            c += hs[q].x * hd[q].x + hs[q].y * hd[q].y + hs[q].z * hd[q].z + hs[q].w * hd[q].w;
        c += __shfl_xor_sync(0xFFFFFFFFu, c, 1);
        c += __shfl_xor_sync(0xFFFFFFFFu, c, 2);
        c += __shfl_xor_sync(0xFFFFFFFFu, c, 4);

        float lin = lins + g_lin_d[dst];
        float sig = __fdividef(1.f, 1.f + __expf(-c));
        float z = lin * sig;
        float lr = (z >= 0.f) ? z : ALPHA * z;
        float e = valid ? __expf(-lr) : 0.f;

        #pragma unroll
        for (int q = 0; q < 4; q++) {
            acc[q].x += e * hd[q].x;
            acc[q].y += e * hd[q].y;
            acc[q].z += e * hd[q].z;
            acc[q].w += e * hd[q].w;
        }
        rs += e;
    }

    // reduce across the 4 neighbor-groups (lanes sub, sub+8, sub+16, sub+24)
    #pragma unroll
    for (int o = 8; o <= 16; o <<= 1) {
        #pragma unroll
        for (int q = 0; q < 4; q++) {
            acc[q].x += __shfl_xor_sync(0xFFFFFFFFu, acc[q].x, o);
            acc[q].y += __shfl_xor_sync(0xFFFFFFFFu, acc[q].y, o);
            acc[q].z += __shfl_xor_sync(0xFFFFFFFFu, acc[q].z, o);
            acc[q].w += __shfl_xor_sync(0xFFFFFFFFu, acc[q].w, o);
        }
        rs += __shfl_xor_sync(0xFFFFFFFFu, rs, o);
    }

    if (grp == 0) {
        float inv = __fdividef(1.f, rs + 1e-8f);
        #pragma unroll
        for (int q = 0; q < 4; q++) {
            float4 v = make_float4(acc[q].x * inv, acc[q].y * inv,
                                   acc[q].z * inv, acc[q].w * inv);
            v.x = (v.x > 0.f) ? v.x : expm1f(v.x);
            v.y = (v.y > 0.f) ? v.y : expm1f(v.y);
            v.z = (v.z > 0.f) ? v.z : expm1f(v.z);
            v.w = (v.w > 0.f) ? v.w : expm1f(v.w);
            *reinterpret_cast<float4*>(&out[(size_t)node * F_OUT + q * 32 + sub * 4]) = v;
        }
    }
}

// ---------------------------------------------------------------------------
extern "C" void kernel_launch(void* const* d_in, const int* in_sizes, int n_in,
                              void* d_out, int out_size) {
    const float* x  = (const float*)d_in[0];
    const int*   ei = (const int*)d_in[1];
    const float* W  = (const float*)d_in[2];
    const float* a  = (const float*)d_in[3];
    float* out = (float*)d_out;

    const int E = in_sizes[1] / 2;

    cudaFuncSetAttribute(gemm_fill_kernel,
                         cudaFuncAttributeMaxDynamicSharedMemorySize, SMEM_TOTAL);

    setup_kernel<<<ZBLK + WBLK + 1, 256>>>(W, a);
    gemm_fill_kernel<<<NTILES + (E + 255) / 256, 256, SMEM_TOTAL>>>(x, ei, E);
    node_kernel<<<N_NODES, 32>>>(out);
}

// round 16
// speedup vs baseline: 1.5506x; 1.1156x over previous
#include <cuda_runtime.h>
#include <math.h>
#include <stdint.h>

#define N_NODES 50000
#define E_MAX   800000
#define F_IN    256
#define F_OUT   128
#define ALPHA   0.2f
#define BUCKET  64          // slots per node; mean deg 16, sigma 4 -> 12-sigma margin

#define GTILE_M 64
#define KCHUNK  64
#define NCHUNKS (F_IN / KCHUNK)                       // 4
#define NTILES  ((N_NODES + GTILE_M - 1) / GTILE_M)   // 782
#define WSSTRIDE (NCHUNKS * F_OUT * KCHUNK)           // 32768

// smem: 3 A-split tiles (64x128B = 8KB) + 3 B-split tiles (128x128B = 16KB)
#define ATILEB  8192
#define BTILEB  16384
#define A_OFF(s) ((s) * ATILEB)
#define B_OFF(s) (3 * ATILEB + (s) * BTILEB)
#define SMEM_TOTAL (3 * ATILEB + 3 * BTILEB)          // 73728

// setup kernel grid split
#define ZBLK ((N_NODES + 255) / 256)                  // 196
#define WBLK ((F_IN * F_OUT + 255) / 256)             // 128
#define ABLK 8                                        // asum partial blocks

// Scratch (__device__ globals: allocation-free)
__device__ float g_h[N_NODES * F_OUT];
__device__ float g_lin_s[N_NODES];
__device__ float g_lin_d[N_NODES];
__device__ float g_asum_part[ABLK][2 * F_OUT];
__device__ unsigned short g_wb[3 * WSSTRIDE];   // [split][chunk][n][kk]
__device__ int g_deg[N_NODES];
__device__ int g_edst[N_NODES * BUCKET];        // bucketed adjacency

// ---------------------------------------------------------------------------
__device__ __forceinline__ uint32_t smem_u32(const void* p) {
    uint32_t a;
    asm("{ .reg .u64 t; cvta.to.shared.u64 t, %1; cvt.u32.u64 %0, t; }"
        : "=r"(a) : "l"(p));
    return a;
}

__device__ __forceinline__ void ldsm4(uint32_t* r, uint32_t addr) {
    asm volatile("ldmatrix.sync.aligned.m8n8.x4.shared.b16 {%0,%1,%2,%3}, [%4];"
                 : "=r"(r[0]), "=r"(r[1]), "=r"(r[2]), "=r"(r[3]) : "r"(addr));
}

__device__ __forceinline__ void mma16816(float* d, const uint32_t* a, const uint32_t* b) {
    asm volatile(
        "mma.sync.aligned.m16n8k16.row.col.f32.bf16.bf16.f32 "
        "{%0,%1,%2,%3},{%4,%5,%6,%7},{%8,%9},{%0,%1,%2,%3};"
        : "+f"(d[0]), "+f"(d[1]), "+f"(d[2]), "+f"(d[3])
        : "r"(a[0]), "r"(a[1]), "r"(a[2]), "r"(a[3]), "r"(b[0]), "r"(b[1]));
}

// exact 3-way bf16 truncation split: v == b0 + b1 + b2 (+ ~2^-24 residual)
__device__ __forceinline__ void split3(float v, uint32_t& b0, uint32_t& b1, uint32_t& b2) {
    uint32_t u = __float_as_uint(v);
    b0 = u >> 16;
    float r1 = v - __uint_as_float(u & 0xFFFF0000u);
    uint32_t u1 = __float_as_uint(r1);
    b1 = u1 >> 16;
    float r2 = r1 - __uint_as_float(u1 & 0xFFFF0000u);
    b2 = __float_as_uint(r2) >> 16;
}

// ---------------------------------------------------------------------------
// Setup: zero degrees | split W | asum partials (8 blocks, 32 rows each)
// ---------------------------------------------------------------------------
__global__ void setup_kernel(const float* __restrict__ W,
                             const float* __restrict__ a) {
    int bid = blockIdx.x;
    if (bid < ZBLK) {
        int i = bid * 256 + threadIdx.x;
        if (i < N_NODES) g_deg[i] = 0;
    } else if (bid < ZBLK + WBLK) {
        int i = (bid - ZBLK) * 256 + threadIdx.x;
        if (i < F_IN * F_OUT) {
            int k = i >> 7, n = i & 127;
            uint32_t b0, b1, b2;
            split3(W[i], b0, b1, b2);
            int base = ((k >> 6) * F_OUT + n) * KCHUNK + (k & 63);
            g_wb[base]                = (unsigned short)b0;
            g_wb[WSSTRIDE + base]     = (unsigned short)b1;
            g_wb[2 * WSSTRIDE + base] = (unsigned short)b2;
        }
    } else {
        int p = bid - ZBLK - WBLK;      // 0..7
        int c = threadIdx.x;
        int r0 = p * 32;
        float s = 0.f;
        #pragma unroll 8
        for (int r = r0; r < r0 + 32; r++)
            s += a[r * (2 * F_OUT) + c];
        g_asum_part[p][c] = s;
    }
}

// ---------------------------------------------------------------------------
// Merged GEMM + adjacency-fill kernel.
// Blocks [0, NTILES): tensor-core GEMM (h = X @ W via exact bf16x3 split).
// Blocks [NTILES, ...): bucketed adjacency fill (concurrent backfill).
// ---------------------------------------------------------------------------
__global__ void __launch_bounds__(256, 2)
gemm_fill_kernel(const float* __restrict__ X, const int* __restrict__ ei, int E) {
    if (blockIdx.x >= NTILES) {
        // ---------------- fill branch ----------------
        int e = (blockIdx.x - NTILES) * 256 + threadIdx.x;
        if (e < E) {
            int src = ei[e];
            int p = atomicAdd(&g_deg[src], 1);
            g_edst[src * BUCKET + p] = ei[E + e];
        }
        return;
    }

    // ---------------- GEMM branch ----------------
    extern __shared__ char smem[];
    __shared__ float s_asum[2 * F_OUT];
    __shared__ float s_lin[2][GTILE_M];
    const uint32_t sb = smem_u32(smem);
    const int tid = threadIdx.x;
    const int lane = tid & 31;
    const int wid = tid >> 5;
    const int warp_m = wid & 1;
    const int warp_n = wid >> 1;
    const int block_row = blockIdx.x * GTILE_M;

    {
        float s = 0.f;
        #pragma unroll
        for (int p = 0; p < ABLK; p++)
            s += g_asum_part[p][tid];
        s_asum[tid] = s;
    }
    if (tid < GTILE_M) { s_lin[0][tid] = 0.f; s_lin[1][tid] = 0.f; }

    float acc[2][4][4];
    #pragma unroll
    for (int mt = 0; mt < 2; mt++)
        #pragma unroll
        for (int nt = 0; nt < 4; nt++)
            #pragma unroll
            for (int j = 0; j < 4; j++) acc[mt][nt][j] = 0.f;

    for (int c = 0; c < NCHUNKS; c++) {
        __syncthreads();
        // ---- fill A: load X fp32, split to 3 bf16 tiles (swizzled [m][k]) ----
        #pragma unroll
        for (int i = 0; i < 2; i++) {
            int u = tid + i * 256;
            int row = u >> 3;
            int kseg = u & 7;
            int gr = block_row + row;
            float4 v0, v1;
            if (gr < N_NODES) {
                const float* p = X + (size_t)gr * F_IN + c * KCHUNK + kseg * 8;
                v0 = *reinterpret_cast<const float4*>(p);
                v1 = *reinterpret_cast<const float4*>(p + 4);
            } else {
                v0 = make_float4(0.f, 0.f, 0.f, 0.f);
                v1 = v0;
            }
            float vals[8] = {v0.x, v0.y, v0.z, v0.w, v1.x, v1.y, v1.z, v1.w};
            uint32_t w0[4], w1[4], w2[4];
            #pragma unroll
            for (int j = 0; j < 4; j++) {
                uint32_t l0, l1, l2, h0, h1, h2;
                split3(vals[2 * j], l0, l1, l2);
                split3(vals[2 * j + 1], h0, h1, h2);
                w0[j] = l0 | (h0 << 16);
                w1[j] = l1 | (h1 << 16);
                w2[j] = l2 | (h2 << 16);
            }
            uint32_t off = (uint32_t)(row * 128) + (uint32_t)((kseg ^ (row & 7)) << 4);
            *reinterpret_cast<uint4*>(smem + A_OFF(0) + off) = make_uint4(w0[0], w0[1], w0[2], w0[3]);
            *reinterpret_cast<uint4*>(smem + A_OFF(1) + off) = make_uint4(w1[0], w1[1], w1[2], w1[3]);
            *reinterpret_cast<uint4*>(smem + A_OFF(2) + off) = make_uint4(w2[0], w2[1], w2[2], w2[3]);
        }
        // ---- fill B: pre-split bf16 from g_wb (swizzled [n][k]) ----
        #pragma unroll
        for (int i = 0; i < 12; i++) {
            int u = tid + i * 256;
            int s = u >> 10;
            int rem = u & 1023;
            int n = rem >> 3;
            int kseg = rem & 7;
            uint4 v = *reinterpret_cast<const uint4*>(
                g_wb + s * WSSTRIDE + ((c * F_OUT + n) * KCHUNK + kseg * 8));
            uint32_t off = (uint32_t)(n * 128) + (uint32_t)((kseg ^ (n & 7)) << 4);
            *reinterpret_cast<uint4*>(smem + B_OFF(s) + off) = v;
        }
        __syncthreads();

        // ---- compute: A-split sa pairs with B-splits 0..(2-sa) ----
        #pragma unroll
        for (int sa = 0; sa < 3; sa++) {
            const int nb = 3 - sa;
            const uint32_t abase = sb + A_OFF(sa);
            #pragma unroll
            for (int ks = 0; ks < 4; ks++) {
                uint32_t afr[2][4];
                #pragma unroll
                for (int mt = 0; mt < 2; mt++) {
                    int row = warp_m * 32 + mt * 16 + (lane & 15);
                    int kseg = ks * 2 + (lane >> 4);
                    ldsm4(afr[mt], abase + row * 128 + ((kseg ^ (row & 7)) << 4));
                }
                for (int sbi = 0; sbi < nb; sbi++) {
                    const uint32_t bbase = sb + B_OFF(sbi);
                    uint32_t bfr[2][4];
                    #pragma unroll
                    for (int np = 0; np < 2; np++) {
                        int n = warp_n * 32 + np * 16 + ((lane & 7) | ((lane >> 4) << 3));
                        int kseg = ks * 2 + ((lane >> 3) & 1);
                        ldsm4(bfr[np], bbase + n * 128 + ((kseg ^ (n & 7)) << 4));
                    }
                    #pragma unroll
                    for (int mt = 0; mt < 2; mt++)
                        #pragma unroll
                        for (int nt = 0; nt < 4; nt++)
                            mma16816(acc[mt][nt], afr[mt], &bfr[nt >> 1][(nt & 1) * 2]);
                }
            }
        }
    }

    // ---- epilogue: write h + lin partials ----
    #pragma unroll
    for (int mt = 0; mt < 2; mt++) {
        float ps0 = 0.f, pd0 = 0.f, ps1 = 0.f, pd1 = 0.f;
        #pragma unroll
        for (int nt = 0; nt < 4; nt++) {
            int row = block_row + warp_m * 32 + mt * 16 + (lane >> 2);
            int col = warp_n * 32 + nt * 8 + (lane & 3) * 2;
            float a1x = s_asum[col],         a1y = s_asum[col + 1];
            float a2x = s_asum[F_OUT + col], a2y = s_asum[F_OUT + col + 1];
            ps0 += acc[mt][nt][0] * a1x + acc[mt][nt][1] * a1y;
            pd0 += acc[mt][nt][0] * a2x + acc[mt][nt][1] * a2y;
            ps1 += acc[mt][nt][2] * a1x + acc[mt][nt][3] * a1y;
            pd1 += acc[mt][nt][2] * a2x + acc[mt][nt][3] * a2y;
            if (row < N_NODES)
                *reinterpret_cast<float2*>(&g_h[(size_t)row * F_OUT + col]) =
                    make_float2(acc[mt][nt][0], acc[mt][nt][1]);
            if (row + 8 < N_NODES)
                *reinterpret_cast<float2*>(&g_h[(size_t)(row + 8) * F_OUT + col]) =
                    make_float2(acc[mt][nt][2], acc[mt][nt][3]);
        }
        // reduce across the 4 lanes sharing a row (lane&3)
        #pragma unroll
        for (int o = 1; o <= 2; o <<= 1) {
            ps0 += __shfl_xor_sync(0xFFFFFFFFu, ps0, o);
            pd0 += __shfl_xor_sync(0xFFFFFFFFu, pd0, o);
            ps1 += __shfl_xor_sync(0xFFFFFFFFu, ps1, o);
            pd1 += __shfl_xor_sync(0xFFFFFFFFu, pd1, o);
        }
        if ((lane & 3) == 0) {
            int r0 = warp_m * 32 + mt * 16 + (lane >> 2);
            atomicAdd(&s_lin[0][r0], ps0);
            atomicAdd(&s_lin[1][r0], pd0);
            atomicAdd(&s_lin[0][r0 + 8], ps1);
            atomicAdd(&s_lin[1][r0 + 8], pd1);
        }
    }
    __syncthreads();
    if (tid < GTILE_M && block_row + tid < N_NODES) {
        g_lin_s[block_row + tid] = s_lin[0][tid];
        g_lin_d[block_row + tid] = s_lin[1][tid];
    }
}

// ---------------------------------------------------------------------------
// Node kernel: ONE WARP = ONE CTA (fine-grained retirement). Protected body.
// ---------------------------------------------------------------------------
__global__ void __launch_bounds__(32) node_kernel(float* __restrict__ out) {
    int node = blockIdx.x;
    int lane = threadIdx.x;
    int sub = lane & 7;     // feature sub-chunk: floats q*32 + sub*4
    int grp = lane >> 3;    // neighbor group 0..3

    const int start = node * BUCKET;
    const int cnt   = g_deg[node];
    const float* hrow = &g_h[(size_t)node * F_OUT];

    float4 hs[4], acc[4];
    #pragma unroll
    for (int q = 0; q < 4; q++) {
        hs[q] = *reinterpret_cast<const float4*>(hrow + q * 32 + sub * 4);
        acc[q] = make_float4(0.f, 0.f, 0.f, 0.f);
    }
    const float lins = g_lin_s[node];
    float rs = 0.f;

    for (int j = 0; j < cnt; j += 4) {
        int mye = j + grp;
        bool valid = (mye < cnt);
        int dst = valid ? g_edst[start + mye] : 0;
        const float* hdp = &g_h[(size_t)dst * F_OUT];
        float4 hd[4];
        #pragma unroll
        for (int q = 0; q < 4; q++)
            hd[q] = *reinterpret_cast<const float4*>(hdp + q * 32 + sub * 4);

        float c = 0.f;
        #pragma unroll
        for (int q = 0; q < 4; q++)
            c += hs[q].x * hd[q].x + hs[q].y * hd[q].y + hs[q].z * hd[q].z + hs[q].w * hd[q].w;
        c += __shfl_xor_sync(0xFFFFFFFFu, c, 1);
        c += __shfl_xor_sync(0xFFFFFFFFu, c, 2);
        c += __shfl_xor_sync(0xFFFFFFFFu, c, 4);

        float lin = lins + g_lin_d[dst];
        float sig = __fdividef(1.f, 1.f + __expf(-c));
        float z = lin * sig;
        float lr = (z >= 0.f) ? z : ALPHA * z;
        float e = valid ? __expf(-lr) : 0.f;

        #pragma unroll
        for (int q = 0; q < 4; q++) {
            acc[q].x += e * hd[q].x;
            acc[q].y += e * hd[q].y;
            acc[q].z += e * hd[q].z;
            acc[q].w += e * hd[q].w;
        }
        rs += e;
    }

    // reduce across the 4 neighbor-groups (lanes sub, sub+8, sub+16, sub+24)
    #pragma unroll
    for (int o = 8; o <= 16; o <<= 1) {
        #pragma unroll
        for (int q = 0; q < 4; q++) {
            acc[q].x += __shfl_xor_sync(0xFFFFFFFFu, acc[q].x, o);
            acc[q].y += __shfl_xor_sync(0xFFFFFFFFu, acc[q].y, o);
            acc[q].z += __shfl_xor_sync(0xFFFFFFFFu, acc[q].z, o);
            acc[q].w += __shfl_xor_sync(0xFFFFFFFFu, acc[q].w, o);
        }
        rs += __shfl_xor_sync(0xFFFFFFFFu, rs, o);
    }

    if (grp == 0) {
        float inv = __fdividef(1.f, rs + 1e-8f);
        #pragma unroll
        for (int q = 0; q < 4; q++) {
            float4 v = make_float4(acc[q].x * inv, acc[q].y * inv,
                                   acc[q].z * inv, acc[q].w * inv);
            v.x = (v.x > 0.f) ? v.x : expm1f(v.x);
            v.y = (v.y > 0.f) ? v.y : expm1f(v.y);
            v.z = (v.z > 0.f) ? v.z : expm1f(v.z);
            v.w = (v.w > 0.f) ? v.w : expm1f(v.w);
            *reinterpret_cast<float4*>(&out[(size_t)node * F_OUT + q * 32 + sub * 4]) = v;
        }
    }
}

// ---------------------------------------------------------------------------
extern "C" void kernel_launch(void* const* d_in, const int* in_sizes, int n_in,
                              void* d_out, int out_size) {
    const float* x  = (const float*)d_in[0];
    const int*   ei = (const int*)d_in[1];
    const float* W  = (const float*)d_in[2];
    const float* a  = (const float*)d_in[3];
    float* out = (float*)d_out;

    const int E = in_sizes[1] / 2;

    cudaFuncSetAttribute(gemm_fill_kernel,
                         cudaFuncAttributeMaxDynamicSharedMemorySize, SMEM_TOTAL);

    setup_kernel<<<ZBLK + WBLK + ABLK, 256>>>(W, a);
    gemm_fill_kernel<<<NTILES + (E + 255) / 256, 256, SMEM_TOTAL>>>(x, ei, E);
    node_kernel<<<N_NODES, 32>>>(out);
}